// round 16
// baseline (speedup 1.0000x reference)
#include <cuda_runtime.h>
#include <cstdint>

#define NN 100000
#define EE 3200000
#define FIN 1433
#define HID 67
#define H1P 68
#define CLS 7
#define H2P 8

__device__ int   g_cnt[NN];
__device__ int   g_off[NN + 1];
__device__ int   g_cur[NN];
__device__ int   g_nbr[EE];
__device__ float g_dinv[NN];
__device__ float g_h1[(size_t)NN * H1P];
__device__ float g_o1[(size_t)NN * H1P];
__device__ float g_h2[(size_t)NN * H2P];

__global__ void k_init() {
    int i = blockIdx.x * blockDim.x + threadIdx.x;
    if (i < NN) g_cnt[i] = 0;
}

__global__ void k_count(const int* __restrict__ col) {
    int e = blockIdx.x * blockDim.x + threadIdx.x;
    if (e < EE) atomicAdd(&g_cnt[col[e]], 1);
}

__global__ void k_dinv() {
    int i = blockIdx.x * blockDim.x + threadIdx.x;
    if (i < NN) g_dinv[i] = rsqrtf((float)(g_cnt[i] + 1));
}

__global__ void k_scan() {
    __shared__ int wsum[32];
    __shared__ int carry_s;
    int tid = threadIdx.x, lane = tid & 31, wid = tid >> 5;
    if (tid == 0) carry_s = 0;
    __syncthreads();
    for (int base = 0; base < NN; base += 1024) {
        int i = base + tid;
        int v = (i < NN) ? g_cnt[i] : 0;
        int x = v;
        #pragma unroll
        for (int o = 1; o < 32; o <<= 1) {
            int y = __shfl_up_sync(0xffffffffu, x, o);
            if (lane >= o) x += y;
        }
        if (lane == 31) wsum[wid] = x;
        __syncthreads();
        if (wid == 0) {
            int s = wsum[lane];
            #pragma unroll
            for (int o = 1; o < 32; o <<= 1) {
                int y = __shfl_up_sync(0xffffffffu, s, o);
                if (lane >= o) s += y;
            }
            wsum[lane] = s;
        }
        __syncthreads();
        int carry = carry_s;
        int exc = x - v + (wid > 0 ? wsum[wid - 1] : 0);
        if (i < NN) { g_off[i] = carry + exc; g_cur[i] = carry + exc; }
        int tot = wsum[31];
        __syncthreads();
        if (tid == 0) carry_s = carry + tot;
        __syncthreads();
    }
    if (tid == 0) g_off[NN] = carry_s;
}

__global__ void k_scatter(const int* __restrict__ row, const int* __restrict__ col) {
    int e = blockIdx.x * blockDim.x + threadIdx.x;
    if (e < EE) {
        int c = col[e];
        int p = atomicAdd(&g_cur[c], 1);
        g_nbr[p] = row[e];
    }
}

// ---- GEMM1: h1 = x @ W1 (unscaled). cp.async warp-private A staging. ----
#define G1_T   256
#define G1_M   128
#define G1_KC  16
#define G1_NCH 90
#define ASTR   36
#define BSTR   26
#define BBUF   (72 * BSTR)

__device__ __forceinline__ uint32_t tf32(float v) {
    uint32_t u;
    asm("cvt.rna.tf32.f32 %0, %1;" : "=r"(u) : "f"(v));
    return u;
}

__device__ __forceinline__ uint32_t smem_u32(const void* p) {
    uint32_t a;
    asm("{ .reg .u64 t; cvta.to.shared.u64 t, %1; cvt.u32.u64 %0, t; }"
        : "=r"(a) : "l"(p));
    return a;
}

__device__ __forceinline__ void cpa4(uint32_t dst, const float* src) {
    asm volatile("cp.async.ca.shared.global [%0], [%1], 4;"
                 :: "r"(dst), "l"(src) : "memory");
}

__device__ __forceinline__ void mma_tf32(float* d, const uint32_t* a,
                                         uint32_t b0, uint32_t b1) {
    asm volatile(
        "mma.sync.aligned.m16n8k8.row.col.f32.tf32.tf32.f32 "
        "{%0,%1,%2,%3}, {%4,%5,%6,%7}, {%8,%9}, {%0,%1,%2,%3};"
        : "+f"(d[0]), "+f"(d[1]), "+f"(d[2]), "+f"(d[3])
        : "r"(a[0]), "r"(a[1]), "r"(a[2]), "r"(a[3]), "r"(b0), "r"(b1));
}

// stage 32-col pair p for this warp's 16 rows (1 coalesced row-segment per instr)
__device__ __forceinline__ void stage_pair(const float* __restrict__ x, uint32_t asb,
                                           int row0w, int lane, bool rows_ok, int p) {
    int colc = min(32 * p + lane, FIN - 1);   // clamp: dups pair with zeroed B rows
    if (rows_ok) {
        const float* src = x + (size_t)row0w * FIN + colc;
        #pragma unroll
        for (int r = 0; r < 16; r++)
            cpa4(asb + (uint32_t)((r * ASTR + lane) * 4), src + (size_t)r * FIN);
    } else {
        #pragma unroll
        for (int r = 0; r < 16; r++) {
            int gr = min(row0w + r, NN - 1);
            cpa4(asb + (uint32_t)((r * ASTR + lane) * 4), x + (size_t)gr * FIN + colc);
        }
    }
    asm volatile("cp.async.commit_group;" ::: "memory");
}

__global__ __launch_bounds__(G1_T, 3) void k_gemm1(const float* __restrict__ x,
                                                   const float* __restrict__ W1) {
    __shared__ __align__(16) float As[8][16][ASTR];   // warp-private tiles
    __shared__ __align__(16) float Bs[2][BBUF];
    const int il[8] = {0, 2, 4, 6, 1, 3, 5, 7};
    int tid = threadIdx.x;
    int lane = tid & 31, w = tid >> 5;
    int g = lane >> 2, t = lane & 3;
    int row0w = blockIdx.x * G1_M + w * 16;
    bool rows_ok = (row0w + 15) < NN;
    uint32_t asb = smem_u32(&As[w][0][0]);

    bool bstage = tid < 144;
    int bn = tid % 72;
    int bk0 = (tid / 72) * 8;
    bool bnok = bn < HID;
    const float* pB = W1 + bk0 * HID + bn;
    int bsts = bn * BSTR + bk0;

    float acc[9][4];
    #pragma unroll
    for (int nt = 0; nt < 9; nt++)
        #pragma unroll
        for (int q = 0; q < 4; q++) acc[nt][q] = 0.f;

    float pw[8];
    float fra[16];   // fragments for both chunks of current pair

    // prologue: A pair 0 + B chunk 0
    stage_pair(x, asb, row0w, lane, rows_ok, 0);
    if (bstage) {
        #pragma unroll
        for (int j = 0; j < 8; j++) pw[j] = bnok ? pB[j * HID] : 0.f;
        #pragma unroll
        for (int j = 0; j < 8; j++)
            Bs[0][bsts + il[j]] = __uint_as_float(tf32(pw[j]));
    }
    pB += G1_KC * HID;
    asm volatile("cp.async.wait_group 0;" ::: "memory");
    __syncthreads();

    for (int c = 0; c < G1_NCH; c++) {
        int buf = c & 1, h = c & 1;

        if (h == 0) {
            // pair boundary: staged data ready (waited below on prev iter or prologue)
            #pragma unroll
            for (int hh = 0; hh < 2; hh++) {
                int cb = hh * 16;
                #pragma unroll
                for (int j = 0; j < 4; j++) {
                    fra[8 * hh + 2 * j]     = As[w][g][cb + t + 4 * j];
                    fra[8 * hh + 2 * j + 1] = As[w][g + 8][cb + t + 4 * j];
                }
            }
            if (c + 2 < G1_NCH)
                stage_pair(x, asb, row0w, lane, rows_ok, (c >> 1) + 1);
        }

        // B prefetch regs for chunk c+1
        if (c + 1 < G1_NCH) {
            if (c + 1 < 89) {
                if (bstage) {
                    #pragma unroll
                    for (int j = 0; j < 8; j++) pw[j] = bnok ? pB[j * HID] : 0.f;
                }
            } else {
                if (bstage) {
                    #pragma unroll
                    for (int j = 0; j < 8; j++) {
                        int k = 89 * G1_KC + bk0 + j;
                        pw[j] = (bnok && k < FIN) ? pB[j * HID] : 0.f;
                    }
                }
            }
            pB += G1_KC * HID;
        }

        // compute chunk c from fra[8h..8h+7]
        #pragma unroll
        for (int s = 0; s < 2; s++) {
            uint32_t af[4];
            af[0] = __float_as_uint(fra[8 * h + 4 * s + 0]);
            af[1] = __float_as_uint(fra[8 * h + 4 * s + 1]);
            af[2] = __float_as_uint(fra[8 * h + 4 * s + 2]);
            af[3] = __float_as_uint(fra[8 * h + 4 * s + 3]);
            const float* bb = &Bs[buf][g * BSTR + s * 8 + 2 * t];
            #pragma unroll
            for (int nt = 0; nt < 9; nt++) {
                float blo = bb[nt * 8 * BSTR];
                float bhi = bb[nt * 8 * BSTR + 1];
                mma_tf32(acc[nt], af, __float_as_uint(blo), __float_as_uint(bhi));
            }
        }

        if (c + 1 < G1_NCH) {
            if (bstage) {
                #pragma unroll
                for (int j = 0; j < 8; j++)
                    Bs[buf ^ 1][bsts + il[j]] = __uint_as_float(tf32(pw[j]));
            }
            __syncthreads();
            if (h == 1) {   // next iter reads new pair: ensure cp.async landed
                asm volatile("cp.async.wait_group 0;" ::: "memory");
                __syncwarp();
            }
        }
    }

    int r0 = row0w + g, r1 = r0 + 8;
    #pragma unroll
    for (int nt = 0; nt < 9; nt++) {
        int col = nt * 8 + 2 * t;
        if (col < HID) {
            if (r0 < NN) g_h1[(size_t)r0 * H1P + col] = acc[nt][0];
            if (r1 < NN) g_h1[(size_t)r1 * H1P + col] = acc[nt][2];
        }
        if (col + 1 < HID) {
            if (r0 < NN) g_h1[(size_t)r0 * H1P + col + 1] = acc[nt][1];
            if (r1 < NN) g_h1[(size_t)r1 * H1P + col + 1] = acc[nt][3];
        }
    }
}

// ---- agg1: warp/node, lanes 0..16 x float4; dinv folded in ----
__global__ void k_agg1(const float* __restrict__ b1) {
    int warp = (blockIdx.x * blockDim.x + threadIdx.x) >> 5;
    int lane = threadIdx.x & 31;
    if (warp >= NN || lane >= 17) return;
    int c = warp;
    int s = g_off[c], e = g_off[c + 1];

    float4 a = make_float4(0.f, 0.f, 0.f, 0.f);
    const float4* h14 = reinterpret_cast<const float4*>(g_h1);
    for (int i = s; i < e; i++) {
        int r = g_nbr[i];
        float dr = g_dinv[r];
        float4 v = h14[(size_t)r * 17 + lane];
        a.x = fmaf(v.x, dr, a.x); a.y = fmaf(v.y, dr, a.y);
        a.z = fmaf(v.z, dr, a.z); a.w = fmaf(v.w, dr, a.w);
    }
    float dc = g_dinv[c];
    {
        float4 v = h14[(size_t)c * 17 + lane];
        a.x = fmaf(v.x, dc, a.x); a.y = fmaf(v.y, dc, a.y);
        a.z = fmaf(v.z, dc, a.z); a.w = fmaf(v.w, dc, a.w);
    }

    int cb = lane * 4;
    float4 bv;
    bv.x = b1[cb];
    bv.y = (cb + 1 < HID) ? b1[cb + 1] : 0.f;
    bv.z = (cb + 2 < HID) ? b1[cb + 2] : 0.f;
    bv.w = (cb + 3 < HID) ? b1[cb + 3] : 0.f;

    float4 o;
    o.x = dc * a.x + bv.x;  o.x = o.x > 0.f ? o.x : 0.01f * o.x;
    o.y = dc * a.y + bv.y;  o.y = o.y > 0.f ? o.y : 0.01f * o.y;
    o.z = dc * a.z + bv.z;  o.z = o.z > 0.f ? o.z : 0.01f * o.z;
    o.w = dc * a.w + bv.w;  o.w = o.w > 0.f ? o.w : 0.01f * o.w;
    if (lane == 16) o.w = 0.f;
    reinterpret_cast<float4*>(g_o1)[(size_t)c * 17 + lane] = o;
}

#define G2_T 128
__global__ void k_gemm2(const float* __restrict__ W2) {
    __shared__ float w2s[HID * CLS];
    __shared__ float os[G2_T][HID + 2];
    int tid = threadIdx.x;
    int row0 = blockIdx.x * G2_T;
    for (int idx = tid; idx < HID * CLS; idx += G2_T) w2s[idx] = W2[idx];
    for (int idx = tid; idx < G2_T * HID; idx += G2_T) {
        int r = idx / HID, k = idx % HID;
        int gr = row0 + r;
        os[r][k] = (gr < NN) ? g_o1[(size_t)gr * H1P + k] : 0.f;
    }
    __syncthreads();
    int gr = row0 + tid;
    if (gr < NN) {
        float acc[CLS];
        #pragma unroll
        for (int j = 0; j < CLS; j++) acc[j] = 0.f;
        for (int k = 0; k < HID; k++) {
            float v = os[tid][k];
            #pragma unroll
            for (int j = 0; j < CLS; j++) acc[j] += v * w2s[k * CLS + j];
        }
        float d = g_dinv[gr];
        #pragma unroll
        for (int j = 0; j < CLS; j++) g_h2[(size_t)gr * H2P + j] = acc[j] * d;
    }
}

__global__ void k_agg2(const float* __restrict__ b2, float* __restrict__ out) {
    int warp = (blockIdx.x * blockDim.x + threadIdx.x) >> 5;
    int lane = threadIdx.x & 31;
    if (warp >= NN) return;
    int c = warp;
    int s = g_off[c], e = g_off[c + 1];
    float acc[8];
    #pragma unroll
    for (int j = 0; j < 8; j++) acc[j] = 0.f;
    const float4* h24 = reinterpret_cast<const float4*>(g_h2);
    for (int i = s + lane; i < e; i += 32) {
        int r = g_nbr[i];
        float4 lo = h24[(size_t)r * 2];
        float4 hi = h24[(size_t)r * 2 + 1];
        acc[0] += lo.x; acc[1] += lo.y; acc[2] += lo.z; acc[3] += lo.w;
        acc[4] += hi.x; acc[5] += hi.y; acc[6] += hi.z; acc[7] += hi.w;
    }
    #pragma unroll
    for (int j = 0; j < CLS; j++) {
        #pragma unroll
        for (int o = 16; o > 0; o >>= 1)
            acc[j] += __shfl_xor_sync(0xffffffffu, acc[j], o);
    }
    if (lane == 0) {
        float d = g_dinv[c];
        const float* hc = g_h2 + (size_t)c * H2P;
        float v[CLS];
        float m = -1e30f;
        #pragma unroll
        for (int j = 0; j < CLS; j++) {
            v[j] = d * (acc[j] + hc[j]) + b2[j];
            m = fmaxf(m, v[j]);
        }
        float sum = 0.f;
        #pragma unroll
        for (int j = 0; j < CLS; j++) sum += __expf(v[j] - m);
        float lse = m + __logf(sum);
        #pragma unroll
        for (int j = 0; j < CLS; j++) out[(size_t)c * CLS + j] = v[j] - lse;
    }
}

// Fork-join: gemm1 on side stream concurrent with edge chain; join before agg1.
extern "C" void kernel_launch(void* const* d_in, const int* in_sizes, int n_in,
                              void* d_out, int out_size) {
    const float* x  = (const float*)d_in[0];
    const int*   ei = (const int*)d_in[1];
    const float* W1 = (const float*)d_in[2];
    const float* b1 = (const float*)d_in[3];
    const float* W2 = (const float*)d_in[4];
    const float* b2 = (const float*)d_in[5];
    float* out = (float*)d_out;
    const int* row = ei;
    const int* col = ei + EE;

    cudaStream_t s2;
    cudaEvent_t evF, evJ;
    cudaStreamCreateWithFlags(&s2, cudaStreamNonBlocking);
    cudaEventCreateWithFlags(&evF, cudaEventDisableTiming);
    cudaEventCreateWithFlags(&evJ, cudaEventDisableTiming);

    cudaEventRecord(evF, 0);
    cudaStreamWaitEvent(s2, evF, 0);
    k_gemm1<<<(NN + G1_M - 1) / G1_M, G1_T, 0, s2>>>(x, W1);
    cudaEventRecord(evJ, s2);

    k_init<<<(NN + 255) / 256, 256>>>();
    k_count<<<(EE + 255) / 256, 256>>>(col);
    k_dinv<<<(NN + 255) / 256, 256>>>();
    k_scan<<<1, 1024>>>();
    k_scatter<<<(EE + 255) / 256, 256>>>(row, col);

    cudaStreamWaitEvent(0, evJ, 0);
    {
        long long threads = (long long)NN * 32;
        k_agg1<<<(int)((threads + 255) / 256), 256>>>(b1);
    }
    k_gemm2<<<(NN + G2_T - 1) / G2_T, G2_T>>>(W2);
    {
        long long threads = (long long)NN * 32;
        k_agg2<<<(int)((threads + 255) / 256), 256>>>(b2, out);
    }
}